// round 17
// baseline (speedup 1.0000x reference)
#include <cuda_runtime.h>
#include <cstdint>

// Problem constants (fixed by reference: POOL=100, N_TASKS=5 -> F_END=20)
#define KEY_D   768
#define P_FEAT  9216      // EMB_D * HEADS
#define E_P_LEN 8
#define FEND    20
#define TOPKN   10
#define EPSV    1e-12f

// Kernel-1 tiling
#define QPB 8             // queries per block
#define K1_THREADS 640    // 20 warps, warp w <-> key w

// Gate table: q-major, K padded to 32 (zeros for k>=20)
#define QMAX 4096
#define KPAD 32
__device__ float g_gateQ[QMAX * KPAD];

// Kernel-2 (mma.sync tf32) tiling
#define TM 128            // queries per block (4 warps x 32)
#define TN 64             // d-columns per block
#define T_THREADS 128     // 4 warps
#define ASTRIDE 36        // floats per As row (bank: (q*4+k)%32 -> g*4+t distinct)
#define BSTRIDE 72        // floats per Bs row (bank: (8k+n)%32 -> 8t+g distinct)

// ---------------------------------------------------------------------------
// helpers
// ---------------------------------------------------------------------------
__device__ __forceinline__ uint32_t f2tf32(float v) {
    uint32_t r;
    asm("cvt.rna.tf32.f32 %0, %1;" : "=r"(r) : "f"(v));
    return r;
}
__device__ __forceinline__ void mma_tf32(float d[4], const uint32_t a[4],
                                         uint32_t b0, uint32_t b1) {
    asm volatile(
        "mma.sync.aligned.m16n8k8.row.col.f32.tf32.tf32.f32 "
        "{%0,%1,%2,%3}, {%4,%5,%6,%7}, {%8,%9}, {%0,%1,%2,%3};"
        : "+f"(d[0]), "+f"(d[1]), "+f"(d[2]), "+f"(d[3])
        : "r"(a[0]), "r"(a[1]), "r"(a[2]), "r"(a[3]), "r"(b0), "r"(b1));
}

// ---------------------------------------------------------------------------
// Kernel 1 (R16 version): scores + top-10 + softmax -> q-major padded gates.
// ---------------------------------------------------------------------------
__global__ __launch_bounds__(K1_THREADS)
void scores_gate_kernel(const float* __restrict__ x,
                        const float* __restrict__ K,
                        const float* __restrict__ A,
                        int BQ) {
    cudaTriggerProgrammaticLaunchCompletion();

    __shared__ float x_s[QPB][KEY_D];
    __shared__ float sc[QPB][FEND];

    const int q0  = blockIdx.x * QPB;
    const int tid = threadIdx.x;
    const int w   = tid >> 5;
    const int lane = tid & 31;

    float4 a6[6], k6[6];
    {
        const float4* Ar = (const float4*)(A + (size_t)w * KEY_D);
        const float4* Kr = (const float4*)(K + (size_t)w * KEY_D);
#pragma unroll
        for (int i = 0; i < 6; ++i) {
            a6[i] = Ar[lane + 32 * i];
            k6[i] = Kr[lane + 32 * i];
        }
    }
    {
        const float4* src = (const float4*)(x + (size_t)q0 * KEY_D);
        for (int i = tid; i < QPB * KEY_D / 4; i += K1_THREADS)
            ((float4*)&x_s[0][0])[i] = src[i];
    }
    float nk = 0.f;
#pragma unroll
    for (int i = 0; i < 6; ++i) {
        nk = fmaf(k6[i].x, k6[i].x, nk); nk = fmaf(k6[i].y, k6[i].y, nk);
        nk = fmaf(k6[i].z, k6[i].z, nk); nk = fmaf(k6[i].w, k6[i].w, nk);
    }
#pragma unroll
    for (int off = 16; off; off >>= 1)
        nk += __shfl_xor_sync(0xFFFFFFFFu, nk, off);
    const float nKc = fmaxf(sqrtf(nk), EPSV);

    __syncthreads();

#pragma unroll
    for (int q = 0; q < QPB; ++q) {
        const float4* xs4 = (const float4*)x_s[q];
        float dot = 0.f, na = 0.f;
#pragma unroll
        for (int i = 0; i < 6; ++i) {
            float4 xa = xs4[lane + 32 * i];
            float t;
            t = xa.x * a6[i].x; dot = fmaf(t, k6[i].x, dot); na = fmaf(t, t, na);
            t = xa.y * a6[i].y; dot = fmaf(t, k6[i].y, dot); na = fmaf(t, t, na);
            t = xa.z * a6[i].z; dot = fmaf(t, k6[i].z, dot); na = fmaf(t, t, na);
            t = xa.w * a6[i].w; dot = fmaf(t, k6[i].w, dot); na = fmaf(t, t, na);
        }
#pragma unroll
        for (int off = 16; off; off >>= 1) {
            dot += __shfl_xor_sync(0xFFFFFFFFu, dot, off);
            na  += __shfl_xor_sync(0xFFFFFFFFu, na,  off);
        }
        if (lane == 0)
            sc[q][w] = dot / (fmaxf(sqrtf(na), EPSV) * nKc);
    }
    __syncthreads();

    if (tid < QPB && q0 + tid < BQ) {
        float s[FEND];
#pragma unroll
        for (int k = 0; k < FEND; ++k) s[k] = sc[tid][k];
        float tv[TOPKN]; int ti[TOPKN];
#pragma unroll
        for (int j = 0; j < TOPKN; ++j) {
            int bi = 0; float bv = -__int_as_float(0x7F800000);
#pragma unroll
            for (int k = 0; k < FEND; ++k)
                if (s[k] > bv) { bv = s[k]; bi = k; }
            tv[j] = bv; ti[j] = bi;
            s[bi] = -__int_as_float(0x7F800000);
        }
        float m = tv[0], sum = 0.f, e[TOPKN];
#pragma unroll
        for (int j = 0; j < TOPKN; ++j) { e[j] = __expf(tv[j] - m); sum += e[j]; }
        float inv = 1.f / sum;
        float g[KPAD];
#pragma unroll
        for (int k = 0; k < KPAD; ++k) g[k] = 0.f;
#pragma unroll
        for (int j = 0; j < TOPKN; ++j) g[ti[j]] = e[j] * inv;
        float4* gr = (float4*)(g_gateQ + (size_t)(q0 + tid) * KPAD);
#pragma unroll
        for (int k = 0; k < KPAD / 4; ++k)
            gr[k] = make_float4(g[4*k], g[4*k+1], g[4*k+2], g[4*k+3]);
    }
}

// ---------------------------------------------------------------------------
// Kernel 2 (v17, mma.sync tf32): D[128q, 64d] per block.
// Warp = 32q (2 m16 tiles) x 64d (8 n8 tiles), K = 32 (4 k8 steps, padded).
// As[q][36]: a-frag LDS.32 banks = (g*4+t) -> all distinct, conflict-free.
// Bs[k][72]: b-frag LDS.32 banks = (8t+g)  -> all distinct, conflict-free.
// Epilogue: direct STG.64 of c-pairs (8 rows x 32B per instr = 2 wf).
// ---------------------------------------------------------------------------
__global__ __launch_bounds__(T_THREADS, 4)
void expand_mma_kernel(const float* __restrict__ p,
                       float* __restrict__ out,
                       int BQ) {
    __shared__ uint32_t As[TM * ASTRIDE];   // 18 KB (tf32 bits)
    __shared__ uint32_t Bs[KPAD * BSTRIDE]; // 9 KB  (tf32 bits)

    const int tid  = threadIdx.x;
    const int d0   = blockIdx.x * TN;
    const int l    = blockIdx.y;
    const int q0   = blockIdx.z * TM;

    // zero Bs (covers k>=20 pad and stride padding)
    for (int i = tid; i < KPAD * BSTRIDE / 4; i += T_THREADS)
        ((uint4*)Bs)[i] = make_uint4(0, 0, 0, 0);
    __syncthreads();

    // stage B: Bs[k][n] = tf32(p[k, l, d0+n]), n in [0,64)
    for (int i = tid; i < FEND * (TN / 4); i += T_THREADS) {
        int k = i / (TN / 4), nn = i % (TN / 4);
        float4 v = *(const float4*)(p + ((size_t)k * E_P_LEN + l) * P_FEAT
                                    + d0 + nn * 4);
        uint4 t;
        t.x = f2tf32(v.x); t.y = f2tf32(v.y); t.z = f2tf32(v.z); t.w = f2tf32(v.w);
        *(uint4*)(Bs + k * BSTRIDE + nn * 4) = t;
    }

    // gates valid only after kernel 1 completes
    cudaGridDependencySynchronize();

    // stage A: As[m][k] = tf32(g_gateQ[q0+m][k]); thread tid owns row tid
    {
        const float4* gq = (const float4*)(g_gateQ + (size_t)(q0 + tid) * KPAD);
#pragma unroll
        for (int kk = 0; kk < KPAD / 4; ++kk) {
            float4 v = gq[kk];
            uint4 t;
            t.x = f2tf32(v.x); t.y = f2tf32(v.y); t.z = f2tf32(v.z); t.w = f2tf32(v.w);
            *(uint4*)(As + tid * ASTRIDE + kk * 4) = t;
        }
    }
    __syncthreads();

    const int w    = tid >> 5;
    const int lane = tid & 31;
    const int g    = lane >> 2;   // groupID
    const int t    = lane & 3;    // threadID_in_group

    float acc[2][8][4];
#pragma unroll
    for (int qt = 0; qt < 2; ++qt)
#pragma unroll
        for (int nt = 0; nt < 8; ++nt)
#pragma unroll
            for (int r = 0; r < 4; ++r) acc[qt][nt][r] = 0.f;

#pragma unroll
    for (int ks = 0; ks < KPAD / 8; ++ks) {
        // a-fragments for both m16 tiles (conflict-free LDS.32)
        uint32_t a[2][4];
#pragma unroll
        for (int qt = 0; qt < 2; ++qt) {
            int qb = w * 32 + qt * 16;
            a[qt][0] = As[(qb + g)     * ASTRIDE + ks * 8 + t];
            a[qt][1] = As[(qb + g + 8) * ASTRIDE + ks * 8 + t];
            a[qt][2] = As[(qb + g)     * ASTRIDE + ks * 8 + t + 4];
            a[qt][3] = As[(qb + g + 8) * ASTRIDE + ks * 8 + t + 4];
        }
#pragma unroll
        for (int nt = 0; nt < 8; ++nt) {
            uint32_t b0 = Bs[(ks * 8 + t)     * BSTRIDE + nt * 8 + g];
            uint32_t b1 = Bs[(ks * 8 + t + 4) * BSTRIDE + nt * 8 + g];
            mma_tf32(acc[0][nt], a[0], b0, b1);
            mma_tf32(acc[1][nt], a[1], b0, b1);
        }
    }

    // epilogue: c0,c1 -> row (qb+g), cols t*2..t*2+1; c2,c3 -> row (qb+g+8)
    const size_t base = (l < 4) ? 0 : (size_t)BQ * 4;
    const int lrow = l & 3;
#pragma unroll
    for (int qt = 0; qt < 2; ++qt) {
        int q = q0 + w * 32 + qt * 16 + g;
#pragma unroll
        for (int nt = 0; nt < 8; ++nt) {
            int d = d0 + nt * 8 + t * 2;
            if (q < BQ)
                *(float2*)(out + (base + (size_t)q * 4 + lrow) * P_FEAT + d) =
                    make_float2(acc[qt][nt][0], acc[qt][nt][1]);
            if (q + 8 < BQ)
                *(float2*)(out + (base + (size_t)(q + 8) * 4 + lrow) * P_FEAT + d) =
                    make_float2(acc[qt][nt][2], acc[qt][nt][3]);
        }
    }
}

// ---------------------------------------------------------------------------
// Launch
// ---------------------------------------------------------------------------
extern "C" void kernel_launch(void* const* d_in, const int* in_sizes, int n_in,
                              void* d_out, int out_size) {
    int iK, iA, ip;
    if (n_in >= 6 && in_sizes[1] == 1) { iK = 3; iA = 4; ip = 5; }
    else                               { iK = 2; iA = 3; ip = 4; }

    const float* x = (const float*)d_in[0];
    const float* K = (const float*)d_in[iK];
    const float* A = (const float*)d_in[iA];
    const float* p = (const float*)d_in[ip];
    float*     out = (float*)d_out;

    const int BQ = in_sizes[0] / KEY_D;   // 1024 for (4, 256)

    scores_gate_kernel<<<(BQ + QPB - 1) / QPB, K1_THREADS>>>(x, K, A, BQ);

    cudaLaunchConfig_t cfg = {};
    cfg.gridDim  = dim3(P_FEAT / TN, E_P_LEN, (BQ + TM - 1) / TM);
    cfg.blockDim = dim3(T_THREADS, 1, 1);
    cudaLaunchAttribute attrs[1];
    attrs[0].id = cudaLaunchAttributeProgrammaticStreamSerialization;
    attrs[0].val.programmaticStreamSerializationAllowed = 1;
    cfg.attrs = attrs;
    cfg.numAttrs = 1;
    cudaLaunchKernelEx(&cfg, expand_mma_kernel, p, out, BQ);
}